// round 6
// baseline (speedup 1.0000x reference)
#include <cuda_runtime.h>
#include <cstdint>

#define Bq 32
#define Nn 64
#define Hh 128
#define Cc 16
#define SIGMA 0.5f
#define PAD 68

typedef unsigned long long ull;

#define NB64()  asm volatile("bar.sync 1, 64;" ::: "memory")
#define NB128() asm volatile("bar.sync 2, 128;" ::: "memory")

// ---------------- f32x2 packed helpers (sm_103a) ----------------
__device__ __forceinline__ ull ffma2(ull a, ull b, ull c) {
    ull d;
    asm("fma.rn.f32x2 %0, %1, %2, %3;" : "=l"(d) : "l"(a), "l"(b), "l"(c));
    return d;
}
__device__ __forceinline__ ull pack2(float x, float y) {
    ull d;
    asm("mov.b64 %0, {%1, %2};" : "=l"(d) : "f"(x), "f"(y));
    return d;
}
__device__ __forceinline__ float lo2(ull v) { return __uint_as_float((unsigned)v); }
__device__ __forceinline__ float hi2(ull v) { return __uint_as_float((unsigned)(v >> 32)); }

// ---------------- device scratch ----------------
__device__ float g_Anorm[Bq * Nn * Nn];
__device__ float g_h[Bq * Nn * Hh];
__device__ float g_h2[Bq * Nn * Hh];
__device__ float g_xs[4096 * (size_t)(Nn * Hh)];  // per-sample x_new slices
__device__ unsigned long long g_adjbits[Bq * Nn];
__device__ unsigned long long g_maskbits[Bq];
__device__ int g_maxcl[Bq];

// ====== kernel 1: zero adj-accum + prep + h1 = x @ W1 ======
__global__ __launch_bounds__(256) void prep_gemm1(
    const float* __restrict__ x, const float* __restrict__ adj,
    const void* maskp, const float* __restrict__ W1,
    float* __restrict__ outZero, int nzero) {
    int b = blockIdx.x, tid = threadIdx.x;
    __shared__ float deg[Nn];
    __shared__ float xs[Hh * PAD];

    for (int idx = b * 256 + tid; idx < nzero; idx += Bq * 256) outZero[idx] = 0.f;
    if (b == 0 && tid < Bq) g_maxcl[tid] = 0;

    if (tid == 0) {
        unsigned first = ((const unsigned*)maskp)[0];
        int mode = (first == 1u) ? 1 : ((first == 0x3F800000u) ? 2 : 0);
        unsigned long long bits = 0;
        for (int j = 0; j < Nn; j++) {
            bool m;
            if (mode == 0)      m = ((const unsigned char*)maskp)[b * Nn + j] != 0;
            else if (mode == 1) m = ((const int*)maskp)[b * Nn + j] != 0;
            else                m = ((const float*)maskp)[b * Nn + j] != 0.f;
            if (m) bits |= 1ull << j;
        }
        g_maskbits[b] = bits;
    }
    if (tid < Nn) {
        float s = 0.f;
        unsigned long long abits = 0;
        const float* arow = adj + (size_t)b * Nn * Nn + (size_t)tid * Nn;
        for (int j = 0; j < Nn; j++) {
            float v = arow[j];
            if (v > 0.f) abits |= 1ull << j;
            s += (j == tid) ? 1.f : v;
        }
        g_adjbits[b * Nn + tid] = abits;
        deg[tid] = rsqrtf(fmaxf(s, 1.f));
    }
    for (int idx = tid; idx < Nn * Hh; idx += 256) {
        int i = idx >> 7, h = idx & 127;
        xs[h * PAD + i] = x[(size_t)b * Nn * Hh + idx];
    }
    __syncthreads();
    for (int idx = tid; idx < Nn * Nn; idx += 256) {
        int i = idx >> 6, j = idx & 63;
        float a = (i == j) ? 1.f : adj[(size_t)b * Nn * Nn + idx];
        g_Anorm[(size_t)b * Nn * Nn + idx] = deg[i] * a * deg[j];
    }
    int ho = tid & 127, rg = tid >> 7, r0 = rg * 32;
    ull acc2[16];
#pragma unroll
    for (int p = 0; p < 16; p++) acc2[p] = 0ull;
#pragma unroll 4
    for (int k = 0; k < Hh; k++) {
        float w = W1[k * Hh + ho];
        ull ww = pack2(w, w);
        const ulonglong2* xr = (const ulonglong2*)(xs + k * PAD + r0);
#pragma unroll
        for (int q = 0; q < 8; q++) {
            ulonglong2 p0 = xr[q];
            acc2[q * 2 + 0] = ffma2(p0.x, ww, acc2[q * 2 + 0]);
            acc2[q * 2 + 1] = ffma2(p0.y, ww, acc2[q * 2 + 1]);
        }
    }
#pragma unroll
    for (int p = 0; p < 16; p++) {
        g_h[((size_t)b * Nn + r0 + 2 * p + 0) * Hh + ho] = lo2(acc2[p]);
        g_h[((size_t)b * Nn + r0 + 2 * p + 1) * Hh + ho] = hi2(acc2[p]);
    }
}

// ====== kernel 2: xe = relu(A@h1+b1)*mask fused with h2 = xe @ W2 ======
__global__ __launch_bounds__(256) void agg1_gemm2(const float* __restrict__ b1,
                                                  const float* __restrict__ W2) {
    int b = blockIdx.x >> 1;
    int r0 = (blockIdx.x & 1) * 32;
    __shared__ float hs[Nn * Hh];
    __shared__ float at[Nn * 36];
    __shared__ float xet[Hh * 36];
    int tid = threadIdx.x;
    for (int idx = tid; idx < Nn * Hh; idx += 256)
        hs[idx] = g_h[(size_t)b * Nn * Hh + idx];
    for (int idx = tid; idx < 32 * Nn; idx += 256) {
        int il = idx >> 6, j = idx & 63;
        at[j * 36 + il] = g_Anorm[((size_t)b * Nn + r0 + il) * Nn + j];
    }
    __syncthreads();
    int ho = tid & 127, half = tid >> 7;
    int i0 = half * 16;
    float bv = b1[ho];
    float acc[16];
#pragma unroll
    for (int q = 0; q < 16; q++) acc[q] = bv;
#pragma unroll 2
    for (int j = 0; j < Nn; j++) {
        float hv = hs[j * Hh + ho];
        const float4* ar = (const float4*)(at + j * 36 + i0);
#pragma unroll
        for (int q = 0; q < 4; q++) {
            float4 v = ar[q];
            acc[q * 4 + 0] += v.x * hv;
            acc[q * 4 + 1] += v.y * hv;
            acc[q * 4 + 2] += v.z * hv;
            acc[q * 4 + 3] += v.w * hv;
        }
    }
    unsigned long long mb = g_maskbits[b];
#pragma unroll
    for (int q = 0; q < 16; q++) {
        int i = r0 + i0 + q;
        float v = ((mb >> i) & 1ull) ? fmaxf(acc[q], 0.f) : 0.f;
        xet[ho * 36 + i0 + q] = v;
    }
    __syncthreads();
    ull acc2[8];
#pragma unroll
    for (int p = 0; p < 8; p++) acc2[p] = 0ull;
#pragma unroll 4
    for (int k = 0; k < Hh; k++) {
        float w = W2[k * Hh + ho];
        ull ww = pack2(w, w);
        const ulonglong2* xr = (const ulonglong2*)(xet + k * 36 + half * 16);
#pragma unroll
        for (int q = 0; q < 4; q++) {
            ulonglong2 p0 = xr[q];
            acc2[q * 2 + 0] = ffma2(p0.x, ww, acc2[q * 2 + 0]);
            acc2[q * 2 + 1] = ffma2(p0.y, ww, acc2[q * 2 + 1]);
        }
    }
#pragma unroll
    for (int p = 0; p < 8; p++) {
        g_h2[((size_t)b * Nn + r0 + half * 16 + 2 * p + 0) * Hh + ho] = lo2(acc2[p]);
        g_h2[((size_t)b * Nn + r0 + half * 16 + 2 * p + 1) * Hh + ho] = hi2(acc2[p]);
    }
}

// ====== kernel 3: x_emb = relu(A@h2 + b2)*mask ======
__global__ __launch_bounds__(256) void agg2(const float* __restrict__ bias,
                                            float* __restrict__ out_p) {
    int b = blockIdx.x >> 1;
    int r0 = (blockIdx.x & 1) * 32;
    __shared__ float hs[Nn * Hh];
    __shared__ float at[Nn * 36];
    int tid = threadIdx.x;
    for (int idx = tid; idx < Nn * Hh; idx += 256)
        hs[idx] = g_h2[(size_t)b * Nn * Hh + idx];
    for (int idx = tid; idx < 32 * Nn; idx += 256) {
        int il = idx >> 6, j = idx & 63;
        at[j * 36 + il] = g_Anorm[((size_t)b * Nn + r0 + il) * Nn + j];
    }
    __syncthreads();
    int ho = tid & 127, half = tid >> 7;
    int i0 = half * 16;
    float bv = bias[ho];
    float acc[16];
#pragma unroll
    for (int q = 0; q < 16; q++) acc[q] = bv;
#pragma unroll 2
    for (int j = 0; j < Nn; j++) {
        float hv = hs[j * Hh + ho];
        const float4* ar = (const float4*)(at + j * 36 + i0);
#pragma unroll
        for (int q = 0; q < 4; q++) {
            float4 v = ar[q];
            acc[q * 4 + 0] += v.x * hv;
            acc[q * 4 + 1] += v.y * hv;
            acc[q * 4 + 2] += v.z * hv;
            acc[q * 4 + 3] += v.w * hv;
        }
    }
    unsigned long long mb = g_maskbits[b];
#pragma unroll
    for (int q = 0; q < 16; q++) {
        int i = r0 + i0 + q;
        float v = ((mb >> i) & 1ull) ? fmaxf(acc[q], 0.f) : 0.f;
        out_p[((size_t)b * Nn + i) * Hh + ho] = v;
    }
}

// ====== kernel 4: main perturbed clustering (3 blocks/SM) ======
struct SmemK5 {
    float xa[Hh * PAD];   // 34816
    float tt[Hh * PAD];   // 34816
    float lg[Nn * Cc];    // 4096
    unsigned long long adjraw[Nn];
    unsigned long long reach[Nn];
    unsigned long long nodemask[Nn];
    unsigned long long present;
    int concepts[Nn];
    int assign[Nn];
    int ncl;
};

__global__ __launch_bounds__(256, 3) void main_kernel(
    const float* __restrict__ xemb, const float* __restrict__ noise,
    const float* __restrict__ cW1, const float* __restrict__ cb1,
    const float* __restrict__ cW2, const float* __restrict__ cb2,
    float* __restrict__ outAdj, float* __restrict__ outAssign,
    int S, int NC, float invS) {
    extern __shared__ char smemraw[];
    SmemK5* sm = (SmemK5*)smemraw;
    int tid = threadIdx.x;
    int b = blockIdx.x % Bq;
    int chunk = blockIdx.x / Bq;

    if (tid < Nn) sm->adjraw[tid] = g_adjbits[b * Nn + tid];
    unsigned long long mb = g_maskbits[b];
    __syncthreads();

    int ho = tid & 127;
    int half = tid >> 7;
    float cb1v = cb1[ho];
    int maxcl_local = 0;

    for (int s = chunk; s < S; s += NC) {
        int bs = s * Bq + b;

        // ---- load x_all = x_emb + sigma*noise, transposed ----
        const float* xb = xemb + (size_t)b * Nn * Hh;
        const float* nz = noise + (size_t)bs * Nn * Hh;
#pragma unroll 4
        for (int idx = tid; idx < Nn * Hh; idx += 256) {
            int i = idx >> 7, h = idx & 127;
            sm->xa[h * PAD + i] = xb[idx] + SIGMA * nz[idx];
        }
        __syncthreads();

        // ---- t = relu(x_all @ cW1 + cb1), transposed (FFMA2, 2x16 nodes) --
#pragma unroll
        for (int g = 0; g < 2; g++) {
            int r0 = half * 32 + g * 16;
            ull acc2[8];
            ull binit = pack2(cb1v, cb1v);
#pragma unroll
            for (int p = 0; p < 8; p++) acc2[p] = binit;
#pragma unroll 4
            for (int k = 0; k < Hh; k++) {
                float w = cW1[k * Hh + ho];
                ull ww = pack2(w, w);
                const ulonglong2* xr = (const ulonglong2*)(sm->xa + k * PAD + r0);
#pragma unroll
                for (int q = 0; q < 4; q++) {
                    ulonglong2 p0 = xr[q];
                    acc2[q * 2 + 0] = ffma2(p0.x, ww, acc2[q * 2 + 0]);
                    acc2[q * 2 + 1] = ffma2(p0.y, ww, acc2[q * 2 + 1]);
                }
            }
            float4* to = (float4*)(sm->tt + ho * PAD + r0);
#pragma unroll
            for (int q = 0; q < 4; q++) {
                float4 v;
                v.x = fmaxf(lo2(acc2[q * 2 + 0]), 0.f);
                v.y = fmaxf(hi2(acc2[q * 2 + 0]), 0.f);
                v.z = fmaxf(lo2(acc2[q * 2 + 1]), 0.f);
                v.w = fmaxf(hi2(acc2[q * 2 + 1]), 0.f);
                to[q] = v;
            }
        }
        __syncthreads();

        // ---- logits = t @ cW2 + cb2 (FFMA2, cW2 via L1) ----
        {
            int i = tid & 63, cg = tid >> 6;
            ull a01 = pack2(cb2[cg * 4 + 0], cb2[cg * 4 + 1]);
            ull a23 = pack2(cb2[cg * 4 + 2], cb2[cg * 4 + 3]);
#pragma unroll 4
            for (int k = 0; k < Hh; k++) {
                float tv = sm->tt[k * PAD + i];
                ull tvv = pack2(tv, tv);
                ulonglong2 cv = ((const ulonglong2*)(cW2 + k * Cc + cg * 4))[0];
                a01 = ffma2(tvv, cv.x, a01);
                a23 = ffma2(tvv, cv.y, a23);
            }
            sm->lg[i * Cc + cg * 4 + 0] = lo2(a01);
            sm->lg[i * Cc + cg * 4 + 1] = hi2(a01);
            sm->lg[i * Cc + cg * 4 + 2] = lo2(a23);
            sm->lg[i * Cc + cg * 4 + 3] = hi2(a23);
        }
        __syncthreads();

        // ======== clustering: warps 0-1 only, named barriers ========
        if (tid < Nn) {
            // argmax (first max)
            float best = sm->lg[tid * Cc];
            int bi = 0;
            for (int c = 1; c < Cc; c++) {
                float v = sm->lg[tid * Cc + c];
                if (v > best) { best = v; bi = c; }
            }
            sm->concepts[tid] = bi;
            NB64();
            // edges + reach init
            int ci = sm->concepts[tid];
            unsigned long long cm = 0;
            for (int j = 0; j < Nn; j++)
                if (sm->concepts[j] == ci) cm |= 1ull << j;
            bool mi = (mb >> tid) & 1ull;
            unsigned long long e = mi ? (sm->adjraw[tid] & cm & mb) : 0ull;
            sm->reach[tid] = e | (1ull << tid);
            NB64();
            // transitive closure by squaring
            for (int it = 0; it < 6; it++) {
                unsigned long long cur = sm->reach[tid];
                unsigned long long r = cur, t2 = cur;
                while (t2) {
                    int j = __ffsll((long long)t2) - 1;
                    r |= sm->reach[j];
                    t2 &= t2 - 1;
                }
                NB64();
                sm->reach[tid] = r;
                NB64();
            }
            // roots -> present -> rank -> assignments
            if (tid == 0) { sm->present = 0ull; sm->ncl = 0; }
            sm->nodemask[tid] = 0ull;
            NB64();
            int root = 0;
            if (mi) {
                root = __ffsll((long long)sm->reach[tid]) - 1;
                atomicOr(&sm->present, 1ull << root);
            }
            NB64();
            int a = 0;
            if (mi) {
                unsigned long long pm =
                    sm->present & (0xFFFFFFFFFFFFFFFFull >> (63 - root));
                a = __popcll(pm);
                atomicOr(&sm->nodemask[a - 1], 1ull << tid);
                atomicMax(&sm->ncl, a);
            }
            sm->assign[tid] = a;
            outAssign[(size_t)bs * Nn + tid] = (float)a;
        }
        if (tid < 128) NB128();  // assign/nodemask visible to warps 2,3

        if (tid < Nn) {
            // cluster row-OR + adjacency -> global atomics (warps 0,1)
            unsigned long long nm = sm->nodemask[tid];
            unsigned long long ro = 0, t2 = nm;
            while (t2) {
                int j = __ffsll((long long)t2) - 1;
                ro |= sm->adjraw[j];
                t2 &= t2 - 1;
            }
            if (nm) {
                float* arow = outAdj + (size_t)b * Nn * Nn + (size_t)tid * Nn;
                for (int c2 = 0; c2 < Nn; c2++)
                    if (ro & sm->nodemask[c2]) atomicAdd(&arow[c2], invS);
            }
            if (tid == 0) maxcl_local = max(maxcl_local, sm->ncl);
        } else if (tid < 128) {
            // pooling: warps 2,3 -> per-sample x_new slice to scratch
            int tp = tid - 64;           // 0..63
            int h0 = tp, h1 = tp + 64;
            float* dst = g_xs + (size_t)bs * (Nn * Hh);
            for (int c = 0; c < Nn; c++) {
                unsigned long long bits = sm->nodemask[c];
                float s0 = 0.f, s1 = 0.f;
                while (bits) {
                    int i = __ffsll((long long)bits) - 1;
                    s0 += sm->xa[h0 * PAD + i];
                    s1 += sm->xa[h1 * PAD + i];
                    bits &= bits - 1;
                }
                dst[c * Hh + h0] = s0;
                dst[c * Hh + h1] = s1;
            }
        }
        __syncthreads();
    }
    if (tid == 0) atomicMax(&g_maxcl[b], maxcl_local);
}

// ====== kernel 5: x_new mean reduction + mask_new ======
__global__ __launch_bounds__(256) void reduce_kernel(float* __restrict__ outXnew,
                                                     float* __restrict__ outMask,
                                                     int S, float invS) {
    int idx = blockIdx.x * 256 + threadIdx.x;
    if (idx < Bq * Nn * Hh) {
        int b = idx >> 13;
        int rem = idx & 8191;
        const float* p = g_xs + (size_t)b * (Nn * Hh) + rem;
        float acc = 0.f;
#pragma unroll 4
        for (int s = 0; s < S; s++) acc += p[(size_t)s * Bq * (Nn * Hh)];
        outXnew[idx] = acc * invS;
    }
    if (idx < Bq * Nn) {
        int b = idx >> 6, j = idx & 63;
        outMask[idx] = (j < g_maxcl[b]) ? 1.f : 0.f;
    }
}

// ---------------- host launcher ----------------
extern "C" void kernel_launch(void* const* d_in, const int* in_sizes, int n_in,
                              void* d_out, int out_size) {
    const float* x   = (const float*)d_in[0];
    const float* adj = (const float*)d_in[1];
    const void*  msk = d_in[2];
    const float* W1  = (const float*)d_in[3];
    const float* b1  = (const float*)d_in[4];
    const float* W2  = (const float*)d_in[5];
    const float* b2  = (const float*)d_in[6];
    const float* cW1 = (const float*)d_in[7];
    const float* cb1 = (const float*)d_in[8];
    const float* cW2 = (const float*)d_in[9];
    const float* cb2 = (const float*)d_in[10];
    const float* noise = (const float*)d_in[11];

    int S = in_sizes[11] / in_sizes[0];
    if (S <= 0) S = 1;
    if (S > 128) S = 128;  // scratch capacity guard (dataset uses S=100)

    float* out = (float*)d_out;
    size_t offAdj    = (size_t)Bq * Nn * Hh;
    size_t offAssign = offAdj + (size_t)Bq * Nn * Nn;
    size_t offXemb   = offAssign + (size_t)S * Bq * Nn;
    size_t offMask   = offXemb + (size_t)Bq * Nn * Hh;

    cudaFuncSetAttribute(main_kernel, cudaFuncAttributeMaxDynamicSharedMemorySize,
                         (int)sizeof(SmemK5));

    // #1: zero adj-accum + prep + h1
    prep_gemm1<<<Bq, 256>>>(x, adj, msk, W1, out + offAdj, Bq * Nn * Nn);
    // #2: xe + h2 (fused)
    agg1_gemm2<<<Bq * 2, 256>>>(b1, W2);
    // #3: x_emb
    agg2<<<Bq * 2, 256>>>(b2, out + offXemb);
    // #4: main (ncu capture slot) — single wave at 3 blocks/SM
    int NC = (S < 13) ? S : 13;  // 13*32 = 416 blocks <= 444 resident
    main_kernel<<<NC * Bq, 256, sizeof(SmemK5)>>>(
        out + offXemb, noise, cW1, cb1, cW2, cb2,
        out + offAdj, out + offAssign, S, NC, 1.0f / (float)S);
    // #5: x_new mean + mask_new
    reduce_kernel<<<(Bq * Nn * Hh + 255) / 256, 256>>>(out, out + offMask, S,
                                                       1.0f / (float)S);
}

// round 7
// speedup vs baseline: 1.2081x; 1.2081x over previous
#include <cuda_runtime.h>
#include <cstdint>

#define Bq 32
#define Nn 64
#define Hh 128
#define Cc 16
#define SIGMA 0.5f
#define PAD 68
#define TTS 132  // tt2 row stride (floats), mult of 4

typedef unsigned long long ull;

#define NB64()  asm volatile("bar.sync 1, 64;" ::: "memory")

// ---------------- f32x2 packed helpers (sm_103a) ----------------
__device__ __forceinline__ ull ffma2(ull a, ull b, ull c) {
    ull d;
    asm("fma.rn.f32x2 %0, %1, %2, %3;" : "=l"(d) : "l"(a), "l"(b), "l"(c));
    return d;
}
__device__ __forceinline__ ull pack2(float x, float y) {
    ull d;
    asm("mov.b64 %0, {%1, %2};" : "=l"(d) : "f"(x), "f"(y));
    return d;
}
__device__ __forceinline__ float lo2(ull v) { return __uint_as_float((unsigned)v); }
__device__ __forceinline__ float hi2(ull v) { return __uint_as_float((unsigned)(v >> 32)); }

// ---------------- device scratch ----------------
__device__ float g_Anorm[Bq * Nn * Nn];
__device__ float g_h[Bq * Nn * Hh];
__device__ float g_h2[Bq * Nn * Hh];
__device__ unsigned long long g_adjbits[Bq * Nn];
__device__ unsigned long long g_maskbits[Bq];
__device__ int g_maxcl[Bq];

// ====== kernel 1: zero accums + prep + h1 = x @ W1 ======
__global__ __launch_bounds__(256) void prep_gemm1(
    const float* __restrict__ x, const float* __restrict__ adj,
    const void* maskp, const float* __restrict__ W1,
    float* __restrict__ outZero, int nzero) {
    int b = blockIdx.x, tid = threadIdx.x;
    __shared__ float deg[Nn];
    __shared__ float xs[Hh * PAD];

    for (int idx = b * 256 + tid; idx < nzero; idx += Bq * 256) outZero[idx] = 0.f;
    if (b == 0 && tid < Bq) g_maxcl[tid] = 0;

    if (tid == 0) {
        unsigned first = ((const unsigned*)maskp)[0];
        int mode = (first == 1u) ? 1 : ((first == 0x3F800000u) ? 2 : 0);
        unsigned long long bits = 0;
        for (int j = 0; j < Nn; j++) {
            bool m;
            if (mode == 0)      m = ((const unsigned char*)maskp)[b * Nn + j] != 0;
            else if (mode == 1) m = ((const int*)maskp)[b * Nn + j] != 0;
            else                m = ((const float*)maskp)[b * Nn + j] != 0.f;
            if (m) bits |= 1ull << j;
        }
        g_maskbits[b] = bits;
    }
    if (tid < Nn) {
        float s = 0.f;
        unsigned long long abits = 0;
        const float* arow = adj + (size_t)b * Nn * Nn + (size_t)tid * Nn;
        for (int j = 0; j < Nn; j++) {
            float v = arow[j];
            if (v > 0.f) abits |= 1ull << j;
            s += (j == tid) ? 1.f : v;
        }
        g_adjbits[b * Nn + tid] = abits;
        deg[tid] = rsqrtf(fmaxf(s, 1.f));
    }
    for (int idx = tid; idx < Nn * Hh; idx += 256) {
        int i = idx >> 7, h = idx & 127;
        xs[h * PAD + i] = x[(size_t)b * Nn * Hh + idx];
    }
    __syncthreads();
    for (int idx = tid; idx < Nn * Nn; idx += 256) {
        int i = idx >> 6, j = idx & 63;
        float a = (i == j) ? 1.f : adj[(size_t)b * Nn * Nn + idx];
        g_Anorm[(size_t)b * Nn * Nn + idx] = deg[i] * a * deg[j];
    }
    int ho = tid & 127, rg = tid >> 7, r0 = rg * 32;
    ull acc2[16];
#pragma unroll
    for (int p = 0; p < 16; p++) acc2[p] = 0ull;
#pragma unroll 4
    for (int k = 0; k < Hh; k++) {
        float w = W1[k * Hh + ho];
        ull ww = pack2(w, w);
        const ulonglong2* xr = (const ulonglong2*)(xs + k * PAD + r0);
#pragma unroll
        for (int q = 0; q < 8; q++) {
            ulonglong2 p0 = xr[q];
            acc2[q * 2 + 0] = ffma2(p0.x, ww, acc2[q * 2 + 0]);
            acc2[q * 2 + 1] = ffma2(p0.y, ww, acc2[q * 2 + 1]);
        }
    }
#pragma unroll
    for (int p = 0; p < 16; p++) {
        g_h[((size_t)b * Nn + r0 + 2 * p + 0) * Hh + ho] = lo2(acc2[p]);
        g_h[((size_t)b * Nn + r0 + 2 * p + 1) * Hh + ho] = hi2(acc2[p]);
    }
}

// ====== kernel 2: xe = relu(A@h1+b1)*mask fused with h2 = xe @ W2 ======
__global__ __launch_bounds__(256) void agg1_gemm2(const float* __restrict__ b1,
                                                  const float* __restrict__ W2) {
    int b = blockIdx.x >> 1;
    int r0 = (blockIdx.x & 1) * 32;
    __shared__ float hs[Nn * Hh];
    __shared__ float at[Nn * 36];
    __shared__ float xet[Hh * 36];
    int tid = threadIdx.x;
    for (int idx = tid; idx < Nn * Hh; idx += 256)
        hs[idx] = g_h[(size_t)b * Nn * Hh + idx];
    for (int idx = tid; idx < 32 * Nn; idx += 256) {
        int il = idx >> 6, j = idx & 63;
        at[j * 36 + il] = g_Anorm[((size_t)b * Nn + r0 + il) * Nn + j];
    }
    __syncthreads();
    int ho = tid & 127, half = tid >> 7;
    int i0 = half * 16;
    float bv = b1[ho];
    float acc[16];
#pragma unroll
    for (int q = 0; q < 16; q++) acc[q] = bv;
#pragma unroll 2
    for (int j = 0; j < Nn; j++) {
        float hv = hs[j * Hh + ho];
        const float4* ar = (const float4*)(at + j * 36 + i0);
#pragma unroll
        for (int q = 0; q < 4; q++) {
            float4 v = ar[q];
            acc[q * 4 + 0] += v.x * hv;
            acc[q * 4 + 1] += v.y * hv;
            acc[q * 4 + 2] += v.z * hv;
            acc[q * 4 + 3] += v.w * hv;
        }
    }
    unsigned long long mb = g_maskbits[b];
#pragma unroll
    for (int q = 0; q < 16; q++) {
        int i = r0 + i0 + q;
        float v = ((mb >> i) & 1ull) ? fmaxf(acc[q], 0.f) : 0.f;
        xet[ho * 36 + i0 + q] = v;
    }
    __syncthreads();
    ull acc2[8];
#pragma unroll
    for (int p = 0; p < 8; p++) acc2[p] = 0ull;
#pragma unroll 4
    for (int k = 0; k < Hh; k++) {
        float w = W2[k * Hh + ho];
        ull ww = pack2(w, w);
        const ulonglong2* xr = (const ulonglong2*)(xet + k * 36 + half * 16);
#pragma unroll
        for (int q = 0; q < 4; q++) {
            ulonglong2 p0 = xr[q];
            acc2[q * 2 + 0] = ffma2(p0.x, ww, acc2[q * 2 + 0]);
            acc2[q * 2 + 1] = ffma2(p0.y, ww, acc2[q * 2 + 1]);
        }
    }
#pragma unroll
    for (int p = 0; p < 8; p++) {
        g_h2[((size_t)b * Nn + r0 + half * 16 + 2 * p + 0) * Hh + ho] = lo2(acc2[p]);
        g_h2[((size_t)b * Nn + r0 + half * 16 + 2 * p + 1) * Hh + ho] = hi2(acc2[p]);
    }
}

// ====== kernel 3: x_emb = relu(A@h2 + b2)*mask ======
__global__ __launch_bounds__(256) void agg2(const float* __restrict__ bias,
                                            float* __restrict__ out_p) {
    int b = blockIdx.x >> 1;
    int r0 = (blockIdx.x & 1) * 32;
    __shared__ float hs[Nn * Hh];
    __shared__ float at[Nn * 36];
    int tid = threadIdx.x;
    for (int idx = tid; idx < Nn * Hh; idx += 256)
        hs[idx] = g_h2[(size_t)b * Nn * Hh + idx];
    for (int idx = tid; idx < 32 * Nn; idx += 256) {
        int il = idx >> 6, j = idx & 63;
        at[j * 36 + il] = g_Anorm[((size_t)b * Nn + r0 + il) * Nn + j];
    }
    __syncthreads();
    int ho = tid & 127, half = tid >> 7;
    int i0 = half * 16;
    float bv = bias[ho];
    float acc[16];
#pragma unroll
    for (int q = 0; q < 16; q++) acc[q] = bv;
#pragma unroll 2
    for (int j = 0; j < Nn; j++) {
        float hv = hs[j * Hh + ho];
        const float4* ar = (const float4*)(at + j * 36 + i0);
#pragma unroll
        for (int q = 0; q < 4; q++) {
            float4 v = ar[q];
            acc[q * 4 + 0] += v.x * hv;
            acc[q * 4 + 1] += v.y * hv;
            acc[q * 4 + 2] += v.z * hv;
            acc[q * 4 + 3] += v.w * hv;
        }
    }
    unsigned long long mb = g_maskbits[b];
#pragma unroll
    for (int q = 0; q < 16; q++) {
        int i = r0 + i0 + q;
        float v = ((mb >> i) & 1ull) ? fmaxf(acc[q], 0.f) : 0.f;
        out_p[((size_t)b * Nn + i) * Hh + ho] = v;
    }
}

// ====== kernel 4: main perturbed clustering (3 blocks/SM, ~56KB smem) ======
struct SmemK5 {
    float xa[Hh * PAD];       // 34816  x_all transposed [h][node]
    float tt2[32 * TTS];      // 16896  relu layer1 out, [node-in-pass][k]
    float lg[Nn * Cc];        // 4096
    unsigned long long adjraw[Nn];
    unsigned long long reach[Nn];
    unsigned long long nodemask[Nn];
    unsigned long long present;
    int concepts[Nn];
    int assign[Nn];
    int ncl;
};

__global__ __launch_bounds__(256, 3) void main_kernel(
    const float* __restrict__ xemb, const float* __restrict__ noise,
    const float* __restrict__ cW1, const float* __restrict__ cb1,
    const float* __restrict__ cW2, const float* __restrict__ cb2,
    float* __restrict__ outXnew, float* __restrict__ outAdj,
    float* __restrict__ outAssign, int S, int NC, float invS) {
    extern __shared__ char smemraw[];
    SmemK5* sm = (SmemK5*)smemraw;
    int tid = threadIdx.x;
    int b = blockIdx.x % Bq;
    int chunk = blockIdx.x / Bq;

    if (tid < Nn) sm->adjraw[tid] = g_adjbits[b * Nn + tid];
    unsigned long long mb = g_maskbits[b];
    __syncthreads();

    // layer1 tile: thread = (hoq = kout-group of 4, ng = node-group of 8)
    int hoq = tid & 31, ng = tid >> 5;
    int myP = ng >> 2;           // which logits pass holds my nodes
    int lnbase = (ng & 3) * 8;   // node offset within pass
    float4 bv1 = *(const float4*)(cb1 + hoq * 4);
    const float* bp1 = (const float*)&bv1;
    float cb2a = cb2[(tid >> 5) * 2 + 0];
    float cb2b = cb2[(tid >> 5) * 2 + 1];
    int maxcl_local = 0;

    for (int s = chunk; s < S; s += NC) {
        int bs = s * Bq + b;

        // ---- stage x_all = x_emb + sigma*noise, transposed ----
        const float* xb = xemb + (size_t)b * Nn * Hh;
        const float* nz = noise + (size_t)bs * Nn * Hh;
#pragma unroll 4
        for (int idx = tid; idx < Nn * Hh; idx += 256) {
            int i = idx >> 7, h = idx & 127;
            sm->xa[h * PAD + i] = xb[idx] + SIGMA * nz[idx];
        }
        __syncthreads();

        // ---- layer1: all 64 nodes in regs; 8 nodes x 4 kouts per thread ----
        ull acc[4][4];  // [kout j][node pair np]
#pragma unroll
        for (int j = 0; j < 4; j++) {
            ull bi = pack2(bp1[j], bp1[j]);
#pragma unroll
            for (int np = 0; np < 4; np++) acc[j][np] = bi;
        }
#pragma unroll 2
        for (int k = 0; k < Hh; k++) {
            const ulonglong2* xr = (const ulonglong2*)(sm->xa + k * PAD + ng * 8);
            ulonglong2 xA = xr[0];
            ulonglong2 xB = xr[1];
            float4 wv = *(const float4*)(cW1 + k * Hh + hoq * 4);
            const float* wp = (const float*)&wv;
#pragma unroll
            for (int j = 0; j < 4; j++) {
                ull wb = pack2(wp[j], wp[j]);
                acc[j][0] = ffma2(xA.x, wb, acc[j][0]);
                acc[j][1] = ffma2(xA.y, wb, acc[j][1]);
                acc[j][2] = ffma2(xB.x, wb, acc[j][2]);
                acc[j][3] = ffma2(xB.y, wb, acc[j][3]);
            }
        }

        // ---- two passes: store my 32-node half of t, then logits ----
#pragma unroll
        for (int P = 0; P < 2; P++) {
            if (myP == P) {
#pragma unroll
                for (int nn = 0; nn < 8; nn++) {
                    int np = nn >> 1;
                    float4 v;
                    if (nn & 1) {
                        v.x = hi2(acc[0][np]); v.y = hi2(acc[1][np]);
                        v.z = hi2(acc[2][np]); v.w = hi2(acc[3][np]);
                    } else {
                        v.x = lo2(acc[0][np]); v.y = lo2(acc[1][np]);
                        v.z = lo2(acc[2][np]); v.w = lo2(acc[3][np]);
                    }
                    v.x = fmaxf(v.x, 0.f); v.y = fmaxf(v.y, 0.f);
                    v.z = fmaxf(v.z, 0.f); v.w = fmaxf(v.w, 0.f);
                    *(float4*)(sm->tt2 + (lnbase + nn) * TTS + hoq * 4) = v;
                }
            }
            __syncthreads();
            // logits for nodes P*32..P*32+31 ; thread = (i node, cg 2-col grp)
            {
                int i = tid & 31, cg = tid >> 5;
                ull a = pack2(cb2a, cb2b);
#pragma unroll 4
                for (int k = 0; k < Hh; k += 4) {
                    float4 tv4 = *(const float4*)(sm->tt2 + i * TTS + k);
                    const float* tp = (const float*)&tv4;
#pragma unroll
                    for (int kk = 0; kk < 4; kk++) {
                        ull tvv = pack2(tp[kk], tp[kk]);
                        ull cv = *(const ull*)(cW2 + (k + kk) * Cc + cg * 2);
                        a = ffma2(tvv, cv, a);
                    }
                }
                sm->lg[(P * 32 + i) * Cc + cg * 2 + 0] = lo2(a);
                sm->lg[(P * 32 + i) * Cc + cg * 2 + 1] = hi2(a);
            }
            __syncthreads();
        }

        // ======== clustering: warps 0-1, named barriers ========
        if (tid < Nn) {
            float best = sm->lg[tid * Cc];
            int bi = 0;
            for (int c = 1; c < Cc; c++) {
                float v = sm->lg[tid * Cc + c];
                if (v > best) { best = v; bi = c; }
            }
            sm->concepts[tid] = bi;
            NB64();
            int ci = sm->concepts[tid];
            unsigned long long cm = 0;
            for (int j = 0; j < Nn; j++)
                if (sm->concepts[j] == ci) cm |= 1ull << j;
            bool mi = (mb >> tid) & 1ull;
            unsigned long long e = mi ? (sm->adjraw[tid] & cm & mb) : 0ull;
            sm->reach[tid] = e | (1ull << tid);
            NB64();
            for (int it = 0; it < 6; it++) {
                unsigned long long cur = sm->reach[tid];
                unsigned long long r = cur, t2 = cur;
                while (t2) {
                    int j = __ffsll((long long)t2) - 1;
                    r |= sm->reach[j];
                    t2 &= t2 - 1;
                }
                NB64();
                sm->reach[tid] = r;
                NB64();
            }
            if (tid == 0) { sm->present = 0ull; sm->ncl = 0; }
            sm->nodemask[tid] = 0ull;
            NB64();
            int root = 0;
            if (mi) {
                root = __ffsll((long long)sm->reach[tid]) - 1;
                atomicOr(&sm->present, 1ull << root);
            }
            NB64();
            int a = 0;
            if (mi) {
                unsigned long long pm =
                    sm->present & (0xFFFFFFFFFFFFFFFFull >> (63 - root));
                a = __popcll(pm);
                atomicOr(&sm->nodemask[a - 1], 1ull << tid);
                atomicMax(&sm->ncl, a);
            }
            sm->assign[tid] = a;
            outAssign[(size_t)bs * Nn + tid] = (float)a;
        }
        __syncthreads();  // nodemask/ncl visible to all

        // ---- concurrent: warps 0-1 adj atomics; warps 2-5 pooling ----
        if (tid < Nn) {
            unsigned long long nm = sm->nodemask[tid];
            if (nm) {
                unsigned long long ro = 0, t2 = nm;
                while (t2) {
                    int j = __ffsll((long long)t2) - 1;
                    ro |= sm->adjraw[j];
                    t2 &= t2 - 1;
                }
                float* arow = outAdj + (size_t)b * Nn * Nn + (size_t)tid * Nn;
                for (int c2 = 0; c2 < Nn; c2++)
                    if (ro & sm->nodemask[c2]) atomicAdd(&arow[c2], invS);
            }
            if (tid == 0) maxcl_local = max(maxcl_local, sm->ncl);
        } else if (tid < 192) {
            int h = tid - 64;  // 0..127
            int nclv = sm->ncl;
            float* xrow = sm->xa + h * PAD;
            float* dst = outXnew + (size_t)b * (Nn * Hh) + h;
            for (int c = 0; c < nclv; c++) {
                unsigned long long bits = sm->nodemask[c];
                float sum = 0.f;
                while (bits) {
                    int i = __ffsll((long long)bits) - 1;
                    sum += xrow[i];
                    bits &= bits - 1;
                }
                atomicAdd(&dst[c * Hh], sum * invS);
            }
        }
        __syncthreads();
    }
    if (tid == 0) atomicMax(&g_maxcl[b], maxcl_local);
}

// ====== kernel 5: mask_new ======
__global__ void finish_kernel(float* outMask) {
    int idx = blockIdx.x * blockDim.x + threadIdx.x;
    if (idx < Bq * Nn) {
        int b = idx >> 6, j = idx & 63;
        outMask[idx] = (j < g_maxcl[b]) ? 1.f : 0.f;
    }
}

// ---------------- host launcher ----------------
extern "C" void kernel_launch(void* const* d_in, const int* in_sizes, int n_in,
                              void* d_out, int out_size) {
    const float* x   = (const float*)d_in[0];
    const float* adj = (const float*)d_in[1];
    const void*  msk = d_in[2];
    const float* W1  = (const float*)d_in[3];
    const float* b1  = (const float*)d_in[4];
    const float* W2  = (const float*)d_in[5];
    const float* b2  = (const float*)d_in[6];
    const float* cW1 = (const float*)d_in[7];
    const float* cb1 = (const float*)d_in[8];
    const float* cW2 = (const float*)d_in[9];
    const float* cb2 = (const float*)d_in[10];
    const float* noise = (const float*)d_in[11];

    int S = in_sizes[11] / in_sizes[0];
    if (S <= 0) S = 1;

    float* out = (float*)d_out;
    size_t offAdj    = (size_t)Bq * Nn * Hh;
    size_t offAssign = offAdj + (size_t)Bq * Nn * Nn;
    size_t offXemb   = offAssign + (size_t)S * Bq * Nn;
    size_t offMask   = offXemb + (size_t)Bq * Nn * Hh;

    cudaFuncSetAttribute(main_kernel, cudaFuncAttributeMaxDynamicSharedMemorySize,
                         (int)sizeof(SmemK5));

    // #1: zero xnew+adj accum + prep + h1
    prep_gemm1<<<Bq, 256>>>(x, adj, msk, W1, out, (int)offAssign);
    // #2: xe + h2 (fused)
    agg1_gemm2<<<Bq * 2, 256>>>(b1, W2);
    // #3: x_emb
    agg2<<<Bq * 2, 256>>>(b2, out + offXemb);
    // #4: main (ncu capture slot) — single wave at 3 blocks/SM
    int NC = (S < 13) ? S : 13;  // 13*32 = 416 <= 444 resident
    main_kernel<<<NC * Bq, 256, sizeof(SmemK5)>>>(
        out + offXemb, noise, cW1, cb1, cW2, cb2,
        out, out + offAdj, out + offAssign, S, NC, 1.0f / (float)S);
    // #5: mask_new
    finish_kernel<<<(Bq * Nn + 255) / 256, 256>>>(out + offMask);
}